// round 2
// baseline (speedup 1.0000x reference)
#include <cuda_runtime.h>

#define NN_DEFAULT 131072
#define D 256
#define NC 64
#define NB 64
#define MAXN 4096
#define SPG 16
#define TILE 8

__device__ int   g_starts[NB + 1];
__device__ float g_Q[NC * D];
__device__ float g_QtT[D * NC];   // [e][c]
__device__ float g_cK[NC];
__device__ float g_P[NB * NC * D];
__device__ float g_sumA[NB * NC];
__device__ float g_H[NB * NC * D];

// ---------------- meta: detect batch dtype (int32 vs int64) + per-graph starts ----------------
__global__ void k_meta(const void* __restrict__ batch, int n) {
    __shared__ int sh_is32;
    int t = threadIdx.x;
    if (t == 0) {
        // read 8 bytes at int64-index n/4 (= byte offset 2n, safe for both widths).
        long long v = ((const long long*)batch)[n / 4];
        sh_is32 = (v < 0 || v >= NB) ? 1 : 0;
    }
    __syncthreads();
    int is32 = sh_is32;
    // lower_bound of value t in sorted batch
    int lo = 0, hi = n;
    while (lo < hi) {
        int mid = (lo + hi) >> 1;
        long long bv = is32 ? (long long)((const int*)batch)[mid]
                            : ((const long long*)batch)[mid];
        if (bv < (long long)t) lo = mid + 1; else hi = mid;
    }
    g_starts[t] = lo;
    if (t == 0) g_starts[NB] = n;
}

// ---------------- Q = Qp @ WQ^T + bQ  (64 blocks, thread = output dim d) ----------------
__global__ void k_q(const float* __restrict__ Qp, const float* __restrict__ Wq,
                    const float* __restrict__ bq) {
    int c = blockIdx.x, d = threadIdx.x;
    __shared__ float qp[D];
    qp[d] = Qp[c * D + d];
    __syncthreads();
    float a0 = 0.f, a1 = 0.f, a2 = 0.f, a3 = 0.f;
    #pragma unroll 4
    for (int e = 0; e < D; e += 4) {
        a0 = fmaf(qp[e + 0], Wq[d * D + e + 0], a0);
        a1 = fmaf(qp[e + 1], Wq[d * D + e + 1], a1);
        a2 = fmaf(qp[e + 2], Wq[d * D + e + 2], a2);
        a3 = fmaf(qp[e + 3], Wq[d * D + e + 3], a3);
    }
    g_Q[c * D + d] = ((a0 + a1) + (a2 + a3)) + bq[d];
}

// ---------------- Qt[c][e] = sum_d Q[c][d] * WK[d][e]; cK[c] = Q[c]·bK ----------------
__global__ void k_qt(const float* __restrict__ Wk, const float* __restrict__ bk) {
    int c = blockIdx.x, e = threadIdx.x;
    __shared__ float q[D];
    q[e] = g_Q[c * D + e];
    __syncthreads();
    float a0 = 0.f, a1 = 0.f;
    #pragma unroll 4
    for (int d = 0; d < D; d += 2) {
        a0 = fmaf(q[d + 0], Wk[(d + 0) * D + e], a0);
        a1 = fmaf(q[d + 1], Wk[(d + 1) * D + e], a1);
    }
    g_QtT[e * NC + c] = a0 + a1;  // transposed store for conflict-free LDS
    if (e == 0) {
        float ck = 0.f;
        for (int d = 0; d < D; d++) ck += q[d] * bk[d];
        g_cK[c] = ck;
    }
}

// ---------------- main fused kernel: scores -> softmax/argmax -> rank-1 accumulate ----------------
extern __shared__ float smem[];

__global__ __launch_bounds__(256, 2) void k_main(const float* __restrict__ x,
                                                 float* __restrict__ argout, int has_arg) {
    float* Qt   = smem;                 // D*NC
    float* Xs   = Qt + D * NC;          // TILE*D
    float* As   = Xs + TILE * D;        // TILE*NC  (doubles as score buffer)
    float* cKs  = As + TILE * NC;       // NC
    float* sAcc = cKs + NC;             // NC

    int t = threadIdx.x;
    int g = blockIdx.x / SPG, sl = blockIdx.x % SPG;
    int s0 = g_starts[g], s1 = g_starts[g + 1];
    int cnt = s1 - s0;
    int chunk = (cnt + SPG - 1) / SPG;
    int i0 = s0 + sl * chunk;
    int i1 = min(i0 + chunk, s1);
    if (i0 >= i1) return;  // uniform across block

    {   // load Qt tile (coalesced float4)
        const float4* src = (const float4*)g_QtT;
        float4* dst = (float4*)Qt;
        for (int r = t; r < D * NC / 4; r += 256) dst[r] = src[r];
    }
    if (t < NC) { cKs[t] = g_cK[t]; sAcc[t] = 0.f; }

    unsigned long long P2[NC / 2];
    #pragma unroll
    for (int j = 0; j < NC / 2; j++) P2[j] = 0ull;
    __syncthreads();

    for (int i = i0; i < i1; i += TILE) {
        int nb = min(TILE, i1 - i);
        {   // load X tile
            const float4* src = (const float4*)(x + (size_t)i * D);
            float4* dst = (float4*)Xs;
            int nt = nb * D / 4;
            for (int r = t; r < nt; r += 256) dst[r] = src[r];
        }
        __syncthreads();

        // Phase B: scores. thread t -> cluster c = t&63, nodes {2*(t>>6), 2*(t>>6)+1}
        {
            int c = t & (NC - 1);
            int n0 = (t >> 6) * 2, n1 = n0 + 1;
            const float* xs0 = Xs + n0 * D;
            const float* xs1 = Xs + n1 * D;
            float p00 = 0.f, p01 = 0.f, p02 = 0.f, p03 = 0.f;
            float p10 = 0.f, p11 = 0.f, p12 = 0.f, p13 = 0.f;
            #pragma unroll 4
            for (int e = 0; e < D; e += 4) {
                float q0 = Qt[(e + 0) * NC + c];
                float q1 = Qt[(e + 1) * NC + c];
                float q2 = Qt[(e + 2) * NC + c];
                float q3 = Qt[(e + 3) * NC + c];
                float4 xa = *(const float4*)(xs0 + e);
                float4 xb = *(const float4*)(xs1 + e);
                p00 = fmaf(xa.x, q0, p00); p01 = fmaf(xa.y, q1, p01);
                p02 = fmaf(xa.z, q2, p02); p03 = fmaf(xa.w, q3, p03);
                p10 = fmaf(xb.x, q0, p10); p11 = fmaf(xb.y, q1, p11);
                p12 = fmaf(xb.z, q2, p12); p13 = fmaf(xb.w, q3, p13);
            }
            float sA = cKs[c] + ((p00 + p01) + (p02 + p03));
            float sB = cKs[c] + ((p10 + p11) + (p12 + p13));
            if (n0 < nb) As[n0 * NC + c] = sA;
            if (n1 < nb) As[n1 * NC + c] = sB;
        }
        __syncthreads();

        // Phase C: per-node softmax over 64 clusters (warp per node) + argmax (first-index ties)
        {
            int w = t >> 5, lane = t & 31;
            if (w < nb) {
                float s0v = As[w * NC + lane], s1v = As[w * NC + lane + 32];
                float p0 = s0v * 0.0625f, p1 = s1v * 0.0625f;
                float m = fmaxf(p0, p1);
                #pragma unroll
                for (int off = 16; off; off >>= 1)
                    m = fmaxf(m, __shfl_xor_sync(0xffffffffu, m, off));
                float e0 = expf(p0 - m), e1 = expf(p1 - m);
                float z = e0 + e1;
                #pragma unroll
                for (int off = 16; off; off >>= 1)
                    z += __shfl_xor_sync(0xffffffffu, z, off);
                float a0 = e0 / z, a1 = e1 / z;
                float bv; int bi;
                if (a0 >= a1) { bv = a0; bi = lane; } else { bv = a1; bi = lane + 32; }
                #pragma unroll
                for (int off = 16; off; off >>= 1) {
                    float ov = __shfl_xor_sync(0xffffffffu, bv, off);
                    int   oi = __shfl_xor_sync(0xffffffffu, bi, off);
                    if (ov > bv || (ov == bv && oi < bi)) { bv = ov; bi = oi; }
                }
                As[w * NC + lane] = a0;
                As[w * NC + lane + 32] = a1;
                if (lane == 0 && has_arg) {
                    int pos = (i + w) - s0;
                    argout[(size_t)g * MAXN + pos] = (float)bi;
                }
            }
        }
        __syncthreads();

        // sumA accumulation (threads < 64)
        if (t < NC) {
            float sa = sAcc[t];
            for (int n = 0; n < nb; n++) sa += As[n * NC + t];
            sAcc[t] = sa;
        }

        // Phase D: P[c][t] += a[c] * x[t], f32x2 over cluster pairs
        for (int n = 0; n < nb; n++) {
            float xv = Xs[n * D + t];
            unsigned long long x2;
            asm("mov.b64 %0, {%1, %1};" : "=l"(x2) : "r"(__float_as_uint(xv)));
            const unsigned long long* a2 = (const unsigned long long*)(As + n * NC);
            #pragma unroll
            for (int j = 0; j < NC / 2; j++) {
                unsigned long long av = a2[j];
                asm("fma.rn.f32x2 %0, %1, %2, %0;" : "+l"(P2[j]) : "l"(av), "l"(x2));
            }
        }
        __syncthreads();
    }

    // flush accumulators
    float* pg = g_P + ((size_t)g * NC) * D + t;
    #pragma unroll
    for (int j = 0; j < NC / 2; j++) {
        unsigned int lo = (unsigned int)(P2[j] & 0xffffffffull);
        unsigned int hi = (unsigned int)(P2[j] >> 32);
        atomicAdd(pg + (size_t)(2 * j) * D,     __uint_as_float(lo));
        atomicAdd(pg + (size_t)(2 * j + 1) * D, __uint_as_float(hi));
    }
    if (t < NC) atomicAdd(&g_sumA[g * NC + t], sAcc[t]);
}

// ---------------- epilogue GEMMs (NT, M=4096, N=256, K=256), 16 rows/block ----------------
template <int MODE>
__global__ __launch_bounds__(256) void k_gemm(const float* __restrict__ Bmat,
                                              const float* __restrict__ bias,
                                              float* __restrict__ Cout) {
    __shared__ float Ash[16 * D];
    int q = threadIdx.x;
    int r0 = blockIdx.x * 16;
    const float* Amat = (MODE == 0) ? g_P : g_H;
    {
        const float4* src = (const float4*)(Amat + (size_t)r0 * D);
        float4* dst = (float4*)Ash;
        for (int r = q; r < 16 * D / 4; r += 256) dst[r] = src[r];
    }
    __syncthreads();
    float acc[16];
    #pragma unroll
    for (int rr = 0; rr < 16; rr++) acc[rr] = 0.f;
    for (int k = 0; k < D; k += 4) {
        float4 b4 = *(const float4*)(Bmat + (size_t)q * D + k);
        #pragma unroll
        for (int rr = 0; rr < 16; rr++) {
            float4 a4 = *(const float4*)(Ash + rr * D + k);
            acc[rr] = fmaf(a4.x, b4.x, acc[rr]);
            acc[rr] = fmaf(a4.y, b4.y, acc[rr]);
            acc[rr] = fmaf(a4.z, b4.z, acc[rr]);
            acc[rr] = fmaf(a4.w, b4.w, acc[rr]);
        }
    }
    #pragma unroll
    for (int rr = 0; rr < 16; rr++) {
        int r = r0 + rr;
        float v = acc[rr];
        if (MODE == 0) {
            v += g_Q[(r & (NC - 1)) * D + q] + g_sumA[r] * bias[q];
            g_H[(size_t)r * D + q] = v;
        } else {
            v += bias[q];
            Cout[(size_t)r * D + q] = fmaxf(v, 0.f);
        }
    }
}

// ---------------- mask output ----------------
__global__ void k_mask(float* __restrict__ maskout) {
    int idx = blockIdx.x * blockDim.x + threadIdx.x;
    if (idx >= NB * MAXN) return;
    int b = idx >> 12, pos = idx & (MAXN - 1);
    int cnt = g_starts[b + 1] - g_starts[b];
    maskout[idx] = (pos < cnt) ? 1.f : 0.f;
}

extern "C" void kernel_launch(void* const* d_in, const int* in_sizes, int n_in,
                              void* d_out, int out_size) {
    const float* x    = (const float*)d_in[0];
    const void*  bat  = d_in[1];
    const float* Qp   = (const float*)d_in[2];
    const float* WQ_w = (const float*)d_in[3];
    const float* WQ_b = (const float*)d_in[4];
    const float* WK_w = (const float*)d_in[5];
    const float* WK_b = (const float*)d_in[6];
    const float* WV_w = (const float*)d_in[7];
    const float* WV_b = (const float*)d_in[8];
    const float* WO_w = (const float*)d_in[9];
    const float* WO_b = (const float*)d_in[10];
    (void)n_in;

    int n_nodes = in_sizes[0] / D;
    float* out = (float*)d_out;
    int has_arg  = out_size >= (NB * NC * D + NB * MAXN);
    int has_mask = out_size >= (NB * NC * D + 2 * NB * MAXN);
    float* argout  = out + NB * NC * D;
    float* maskout = argout + NB * MAXN;

    void *pP = nullptr, *pS = nullptr;
    cudaGetSymbolAddress(&pP, g_P);
    cudaGetSymbolAddress(&pS, g_sumA);
    cudaMemsetAsync(pP, 0, sizeof(float) * NB * NC * D, 0);
    cudaMemsetAsync(pS, 0, sizeof(float) * NB * NC, 0);
    if (has_arg) cudaMemsetAsync(argout, 0, sizeof(float) * NB * MAXN, 0);

    k_meta<<<1, NB>>>(bat, n_nodes);
    k_q<<<NC, 256>>>(Qp, WQ_w, WQ_b);
    k_qt<<<NC, 256>>>(WK_w, WK_b);

    const int smem_main = (D * NC + TILE * D + TILE * NC + NC + NC) * (int)sizeof(float);
    cudaFuncSetAttribute(k_main, cudaFuncAttributeMaxDynamicSharedMemorySize, smem_main);
    k_main<<<NB * SPG, 256, smem_main>>>(x, argout, has_arg);

    k_gemm<0><<<(NB * NC) / 16, 256>>>(WV_w, WV_b, nullptr);
    k_gemm<1><<<(NB * NC) / 16, 256>>>(WO_w, WO_b, out);

    if (has_mask) k_mask<<<(NB * MAXN) / 256, 256>>>(maskout);
}